// round 7
// baseline (speedup 1.0000x reference)
#include <cuda_runtime.h>
#include <math.h>

// Quanvolution: 4-qubit circuit per 2x2 patch, fixed variational unitary.
// e_w(theta) = sum_t CW[w][t] * prod_q g_{t_q}(theta_q), g = (1, cos, sin).
// CW precomputed by a tiny setup kernel (sparse 16-pair enumeration).

#define NQb 4
#define NPp 196
#define NBp 14
#define IMGd 28
#define THREADS_MAIN 224

// CW stored interleaved: g_CW4[t] = {CW_w0[t], CW_w1[t], CW_w2[t], CW_w3[t]}
__device__ float4 g_CW4[81];

static __device__ __forceinline__ int qbit(int z, int q) { return (z >> (3 - q)) & 1; }

__global__ void quanv_setup_kernel(const float* __restrict__ vp /*[2][2][4]*/) {
    __shared__ float Ur[16][16], Ui[16][16];   // [z][col]
    __shared__ float M[4][16][16];
    int tid = threadIdx.x;

    if (tid < 16) {
        float ar[16], ai[16];
#pragma unroll
        for (int z = 0; z < 16; z++) { ar[z] = (z == tid) ? 1.0f : 0.0f; ai[z] = 0.0f; }
#pragma unroll
        for (int l = 0; l < 2; l++) {
            // RY layer
#pragma unroll
            for (int w = 0; w < 4; w++) {
                float h = 0.5f * vp[l * 8 + w];
                float c = cosf(h), s = sinf(h);
                int mask = 8 >> w;
#pragma unroll
                for (int z = 0; z < 16; z++) {
                    if (!(z & mask)) {
                        int z1 = z | mask;
                        float r0 = ar[z], i0 = ai[z], r1 = ar[z1], i1 = ai[z1];
                        ar[z]  = c * r0 - s * r1;  ai[z]  = c * i0 - s * i1;
                        ar[z1] = s * r0 + c * r1;  ai[z1] = s * i0 + c * i1;
                    }
                }
            }
            // RZ layer
#pragma unroll
            for (int w = 0; w < 4; w++) {
                float h = 0.5f * vp[l * 8 + 4 + w];
                float c = cosf(h), s = sinf(h);
                int mask = 8 >> w;
#pragma unroll
                for (int z = 0; z < 16; z++) {
                    float ph_i = (z & mask) ? s : -s;   // exp(+-i h)
                    float r = ar[z], im = ai[z];
                    ar[z] = c * r - ph_i * im;
                    ai[z] = c * im + ph_i * r;
                }
            }
            // CNOT chain 0->1, 1->2, 2->3
#pragma unroll
            for (int cq = 0; cq < 3; cq++) {
                int cm = 8 >> cq, tm = 8 >> (cq + 1);
#pragma unroll
                for (int z = 0; z < 16; z++) {
                    if ((z & cm) && !(z & tm)) {
                        int z1 = z | tm;
                        float tr = ar[z], ti = ai[z];
                        ar[z] = ar[z1]; ai[z] = ai[z1];
                        ar[z1] = tr;    ai[z1] = ti;
                    }
                }
            }
        }
#pragma unroll
        for (int z = 0; z < 16; z++) { Ur[z][tid] = ar[z]; Ui[z][tid] = ai[z]; }
    }
    __syncthreads();

    // M[w][i][j] = sum_z sign_w(z) * Re(conj(U[z,i]) U[z,j])
    for (int k = tid; k < 4 * 256; k += blockDim.x) {
        int w = k >> 8, i = (k >> 4) & 15, j = k & 15;
        float acc = 0.0f;
#pragma unroll
        for (int z = 0; z < 16; z++) {
            float sgn = qbit(z, w) ? -1.0f : 1.0f;
            acc += sgn * (Ur[z][i] * Ur[z][j] + Ui[z][i] * Ui[z][j]);
        }
        M[w][i][j] = acc;
    }
    __syncthreads();

    // Sparse contraction: for fixed t, kcoef is nonzero for exactly 2 (bi,bj)
    // combos per qubit -> 16 contributing (i,j) pairs (not 256).
    //   t_q in {0,1}: bi==bj in {0,1}; coef = 0.5 (t=0) or +-0.5 (t=1, sign=bi)
    //   t_q == 2   : (bi,bj) in {(0,1),(1,0)}; coef = 0.5
    for (int k = tid; k < 4 * 81; k += blockDim.x) {
        int w = k / 81, t = k % 81;
        int td[4] = { t / 27, (t / 9) % 3, (t / 3) % 3, t % 3 };
        float acc = 0.0f;
#pragma unroll
        for (int m = 0; m < 16; m++) {
            int i = 0, j = 0;
            float coef = 1.0f;
#pragma unroll
            for (int q = 0; q < 4; q++) {
                int sel = (m >> (3 - q)) & 1;   // which of the 2 combos
                int tq = td[q];
                int bi, bj; float c;
                if (tq == 2) { bi = sel; bj = 1 - sel; c = 0.5f; }
                else         { bi = sel; bj = sel;
                               c = (tq == 0) ? 0.5f : (sel ? -0.5f : 0.5f); }
                i |= bi << (3 - q);
                j |= bj << (3 - q);
                coef *= c;
            }
            acc += M[w][i][j] * coef;
        }
        // interleaved layout [t][w]
        ((float*)g_CW4)[t * 4 + w] = acc;
    }
}

__global__ __launch_bounds__(THREADS_MAIN) void quanv_main_kernel(
    const float* __restrict__ x, const float* __restrict__ W,
    const float* __restrict__ bias, float* __restrict__ out) {
    __shared__ __align__(16) float xs[784];
    __shared__ __align__(16) float4 cw4[81];
    __shared__ __align__(16) float fs[784];
    __shared__ float logits[10];

    int b = blockIdx.x, tid = threadIdx.x;

    if (tid < 196) reinterpret_cast<float4*>(xs)[tid] =
        reinterpret_cast<const float4*>(x + b * 784)[tid];
    if (tid < 81) cw4[tid] = g_CW4[tid];
    __syncthreads();

    int p = tid;
    if (p < NPp) {
        int pi = p / NBp, pj = p % NBp;
        const float* xp = &xs[pi * 2 * IMGd + pj * 2];
        float th0 = xp[0], th1 = xp[1], th2 = xp[IMGd], th3 = xp[IMGd + 1];

        float g0[3], g1[3], g2[3], g3[3];
        g0[0] = 1.0f; __sincosf(th0, &g0[2], &g0[1]);
        g1[0] = 1.0f; __sincosf(th1, &g1[2], &g1[1]);
        g2[0] = 1.0f; __sincosf(th2, &g2[2], &g2[1]);
        g3[0] = 1.0f; __sincosf(th3, &g3[2], &g3[1]);

        float P01[9], P23[9];
#pragma unroll
        for (int a = 0; a < 3; a++)
#pragma unroll
            for (int c = 0; c < 3; c++) {
                P01[a * 3 + c] = g0[a] * g1[c];
                P23[a * 3 + c] = g2[a] * g3[c];
            }

        float ax = 0.f, ay = 0.f, az = 0.f, aw = 0.f;
#pragma unroll
        for (int u = 0; u < 9; u++) {
            // stage 1: tmp = sum_v CW4[u*9+v] * P23[v]
            float tx = 0.f, ty = 0.f, tz = 0.f, tw = 0.f;
#pragma unroll
            for (int v = 0; v < 9; v++) {
                float4 c4 = cw4[u * 9 + v];
                float pv = P23[v];
                tx += c4.x * pv; ty += c4.y * pv;
                tz += c4.z * pv; tw += c4.w * pv;
            }
            // stage 2: acc += P01[u] * tmp
            float pu = P01[u];
            ax += pu * tx; ay += pu * ty; az += pu * tz; aw += pu * tw;
        }
        reinterpret_cast<float4*>(fs)[p] = make_float4(ax, ay, az, aw);
    }
    __syncthreads();

    int warp = tid >> 5, lane = tid & 31;
    if (warp < 5) {
#pragma unroll
        for (int r = 0; r < 2; r++) {
            int c = warp * 2 + r;
            const float* wr = &W[c * 784];
            float acc = 0.0f;
#pragma unroll 4
            for (int i = lane; i < 784; i += 32) acc += fs[i] * __ldg(&wr[i]);
#pragma unroll
            for (int o = 16; o > 0; o >>= 1) acc += __shfl_xor_sync(0xffffffffu, acc, o);
            if (lane == 0) logits[c] = acc + __ldg(&bias[c]);
        }
    }
    __syncthreads();

    if (tid == 0) {
        float m = -1e30f;
#pragma unroll
        for (int c = 0; c < 10; c++) m = fmaxf(m, logits[c]);
        float s = 0.0f;
#pragma unroll
        for (int c = 0; c < 10; c++) s += expf(logits[c] - m);
        float lg = logf(s) + m;
#pragma unroll
        for (int c = 0; c < 10; c++) out[b * 10 + c] = logits[c] - lg;
    }
}

extern "C" void kernel_launch(void* const* d_in, const int* in_sizes, int n_in,
                              void* d_out, int out_size) {
    const float* x    = (const float*)d_in[0];   // (2048, 28, 28)
    const float* vp   = (const float*)d_in[1];   // (2, 2, 4)
    const float* W    = (const float*)d_in[2];   // (10, 784)
    const float* bias = (const float*)d_in[3];   // (10,)
    float* out = (float*)d_out;                  // (2048, 10)

    int B = in_sizes[0] / (IMGd * IMGd);

    quanv_setup_kernel<<<1, 512>>>(vp);
    quanv_main_kernel<<<B, THREADS_MAIN>>>(x, W, bias, out);
}

// round 8
// speedup vs baseline: 1.0099x; 1.0099x over previous
#include <cuda_runtime.h>
#include <math.h>

// Quanvolution: 4-qubit circuit per 2x2 patch, fixed variational unitary.
// e_w(theta) = sum_t CW[w][t] * prod_q g_{t_q}(theta_q), g = (1, cos, sin).
// CW precomputed by a tiny setup kernel (sparse 16-pair enumeration).

#define NQb 4
#define NPp 196
#define NBp 14
#define IMGd 28
#define THREADS_MAIN 224

// CW stored interleaved: g_CW4[t] = {CW_w0[t], CW_w1[t], CW_w2[t], CW_w3[t]}
__device__ float4 g_CW4[81];

static __device__ __forceinline__ int qbit(int z, int q) { return (z >> (3 - q)) & 1; }

__global__ void quanv_setup_kernel(const float* __restrict__ vp /*[2][2][4]*/) {
    __shared__ float Ur[16][16], Ui[16][16];   // [z][col]
    __shared__ float M[4][16][16];
    int tid = threadIdx.x;

    if (tid < 16) {
        float ar[16], ai[16];
#pragma unroll
        for (int z = 0; z < 16; z++) { ar[z] = (z == tid) ? 1.0f : 0.0f; ai[z] = 0.0f; }
#pragma unroll
        for (int l = 0; l < 2; l++) {
            // RY layer
#pragma unroll
            for (int w = 0; w < 4; w++) {
                float h = 0.5f * vp[l * 8 + w];
                float c = cosf(h), s = sinf(h);
                int mask = 8 >> w;
#pragma unroll
                for (int z = 0; z < 16; z++) {
                    if (!(z & mask)) {
                        int z1 = z | mask;
                        float r0 = ar[z], i0 = ai[z], r1 = ar[z1], i1 = ai[z1];
                        ar[z]  = c * r0 - s * r1;  ai[z]  = c * i0 - s * i1;
                        ar[z1] = s * r0 + c * r1;  ai[z1] = s * i0 + c * i1;
                    }
                }
            }
            // RZ layer
#pragma unroll
            for (int w = 0; w < 4; w++) {
                float h = 0.5f * vp[l * 8 + 4 + w];
                float c = cosf(h), s = sinf(h);
                int mask = 8 >> w;
#pragma unroll
                for (int z = 0; z < 16; z++) {
                    float ph_i = (z & mask) ? s : -s;   // exp(+-i h)
                    float r = ar[z], im = ai[z];
                    ar[z] = c * r - ph_i * im;
                    ai[z] = c * im + ph_i * r;
                }
            }
            // CNOT chain 0->1, 1->2, 2->3
#pragma unroll
            for (int cq = 0; cq < 3; cq++) {
                int cm = 8 >> cq, tm = 8 >> (cq + 1);
#pragma unroll
                for (int z = 0; z < 16; z++) {
                    if ((z & cm) && !(z & tm)) {
                        int z1 = z | tm;
                        float tr = ar[z], ti = ai[z];
                        ar[z] = ar[z1]; ai[z] = ai[z1];
                        ar[z1] = tr;    ai[z1] = ti;
                    }
                }
            }
        }
#pragma unroll
        for (int z = 0; z < 16; z++) { Ur[z][tid] = ar[z]; Ui[z][tid] = ai[z]; }
    }
    __syncthreads();

    // M[w][i][j] = sum_z sign_w(z) * Re(conj(U[z,i]) U[z,j])
    for (int k = tid; k < 4 * 256; k += blockDim.x) {
        int w = k >> 8, i = (k >> 4) & 15, j = k & 15;
        float acc = 0.0f;
#pragma unroll
        for (int z = 0; z < 16; z++) {
            float sgn = qbit(z, w) ? -1.0f : 1.0f;
            acc += sgn * (Ur[z][i] * Ur[z][j] + Ui[z][i] * Ui[z][j]);
        }
        M[w][i][j] = acc;
    }
    __syncthreads();

    // Sparse contraction: for fixed t, kcoef is nonzero for exactly 2 (bi,bj)
    // combos per qubit -> 16 contributing (i,j) pairs (not 256).
    //   t_q in {0,1}: bi==bj in {0,1}; coef = 0.5 (t=0) or +-0.5 (t=1, sign=bi)
    //   t_q == 2   : (bi,bj) in {(0,1),(1,0)}; coef = 0.5
    for (int k = tid; k < 4 * 81; k += blockDim.x) {
        int w = k / 81, t = k % 81;
        int td[4] = { t / 27, (t / 9) % 3, (t / 3) % 3, t % 3 };
        float acc = 0.0f;
#pragma unroll
        for (int m = 0; m < 16; m++) {
            int i = 0, j = 0;
            float coef = 1.0f;
#pragma unroll
            for (int q = 0; q < 4; q++) {
                int sel = (m >> (3 - q)) & 1;   // which of the 2 combos
                int tq = td[q];
                int bi, bj; float c;
                if (tq == 2) { bi = sel; bj = 1 - sel; c = 0.5f; }
                else         { bi = sel; bj = sel;
                               c = (tq == 0) ? 0.5f : (sel ? -0.5f : 0.5f); }
                i |= bi << (3 - q);
                j |= bj << (3 - q);
                coef *= c;
            }
            acc += M[w][i][j] * coef;
        }
        // interleaved layout [t][w]
        ((float*)g_CW4)[t * 4 + w] = acc;
    }
}

__global__ __launch_bounds__(THREADS_MAIN) void quanv_main_kernel(
    const float* __restrict__ x, const float* __restrict__ W,
    const float* __restrict__ bias, float* __restrict__ out) {
    __shared__ __align__(16) float xs[784];
    __shared__ __align__(16) float4 cw4[81];
    __shared__ __align__(16) float fs[784];
    __shared__ float logits[10];

    int b = blockIdx.x, tid = threadIdx.x;

    if (tid < 196) reinterpret_cast<float4*>(xs)[tid] =
        reinterpret_cast<const float4*>(x + b * 784)[tid];
    if (tid < 81) cw4[tid] = g_CW4[tid];
    __syncthreads();

    int p = tid;
    if (p < NPp) {
        int pi = p / NBp, pj = p % NBp;
        const float* xp = &xs[pi * 2 * IMGd + pj * 2];
        float th0 = xp[0], th1 = xp[1], th2 = xp[IMGd], th3 = xp[IMGd + 1];

        float g0[3], g1[3], g2[3], g3[3];
        g0[0] = 1.0f; __sincosf(th0, &g0[2], &g0[1]);
        g1[0] = 1.0f; __sincosf(th1, &g1[2], &g1[1]);
        g2[0] = 1.0f; __sincosf(th2, &g2[2], &g2[1]);
        g3[0] = 1.0f; __sincosf(th3, &g3[2], &g3[1]);

        float P01[9], P23[9];
#pragma unroll
        for (int a = 0; a < 3; a++)
#pragma unroll
            for (int c = 0; c < 3; c++) {
                P01[a * 3 + c] = g0[a] * g1[c];
                P23[a * 3 + c] = g2[a] * g3[c];
            }

        float ax = 0.f, ay = 0.f, az = 0.f, aw = 0.f;
#pragma unroll
        for (int u = 0; u < 9; u++) {
            // stage 1: tmp = sum_v CW4[u*9+v] * P23[v]
            float tx = 0.f, ty = 0.f, tz = 0.f, tw = 0.f;
#pragma unroll
            for (int v = 0; v < 9; v++) {
                float4 c4 = cw4[u * 9 + v];
                float pv = P23[v];
                tx += c4.x * pv; ty += c4.y * pv;
                tz += c4.z * pv; tw += c4.w * pv;
            }
            // stage 2: acc += P01[u] * tmp
            float pu = P01[u];
            ax += pu * tx; ay += pu * ty; az += pu * tz; aw += pu * tw;
        }
        reinterpret_cast<float4*>(fs)[p] = make_float4(ax, ay, az, aw);
    }
    __syncthreads();

    int warp = tid >> 5, lane = tid & 31;
    if (warp < 5) {
#pragma unroll
        for (int r = 0; r < 2; r++) {
            int c = warp * 2 + r;
            const float* wr = &W[c * 784];
            float acc = 0.0f;
#pragma unroll 4
            for (int i = lane; i < 784; i += 32) acc += fs[i] * __ldg(&wr[i]);
#pragma unroll
            for (int o = 16; o > 0; o >>= 1) acc += __shfl_xor_sync(0xffffffffu, acc, o);
            if (lane == 0) logits[c] = acc + __ldg(&bias[c]);
        }
    }
    __syncthreads();

    if (tid == 0) {
        float m = -1e30f;
#pragma unroll
        for (int c = 0; c < 10; c++) m = fmaxf(m, logits[c]);
        float s = 0.0f;
#pragma unroll
        for (int c = 0; c < 10; c++) s += expf(logits[c] - m);
        float lg = logf(s) + m;
#pragma unroll
        for (int c = 0; c < 10; c++) out[b * 10 + c] = logits[c] - lg;
    }
}

extern "C" void kernel_launch(void* const* d_in, const int* in_sizes, int n_in,
                              void* d_out, int out_size) {
    const float* x    = (const float*)d_in[0];   // (2048, 28, 28)
    const float* vp   = (const float*)d_in[1];   // (2, 2, 4)
    const float* W    = (const float*)d_in[2];   // (10, 784)
    const float* bias = (const float*)d_in[3];   // (10,)
    float* out = (float*)d_out;                  // (2048, 10)

    int B = in_sizes[0] / (IMGd * IMGd);

    quanv_setup_kernel<<<1, 512>>>(vp);
    quanv_main_kernel<<<B, THREADS_MAIN>>>(x, W, bias, out);
}